// round 7
// baseline (speedup 1.0000x reference)
#include <cuda_runtime.h>
#include <cuda_bf16.h>
#include <cstdint>
#include <math.h>

// Problem dims
#define BB 2
#define SS 2048
#define DD 1024
#define HH 16
#define DK 64
#define MROWS (BB * SS)   // 4096
#define BHT (BB * HH)     // 32

// -------- scratch (static __device__ globals; no allocation allowed) --------
__device__ float g_S[(size_t)BB * HH * SS * SS];                  // 512 MB raw scores (fp32)
__device__ __nv_bfloat16 g_Ph[(size_t)BB * HH * SS * SS];         // 256 MB P hi
__device__ __nv_bfloat16 g_Pl[(size_t)BB * HH * SS * SS];         // 256 MB P lo

// bf16 hi/lo planes
__device__ __nv_bfloat16 g_Xh[(size_t)MROWS * DD], g_Xl[(size_t)MROWS * DD];
__device__ __nv_bfloat16 g_Zh[(size_t)MROWS * DD], g_Zl[(size_t)MROWS * DD];
__device__ __nv_bfloat16 g_Qh[(size_t)MROWS * DD], g_Ql[(size_t)MROWS * DD];
__device__ __nv_bfloat16 g_Kh[(size_t)MROWS * DD], g_Kl[(size_t)MROWS * DD];
__device__ __nv_bfloat16 g_Ch[(size_t)MROWS * DD], g_Cl[(size_t)MROWS * DD];
__device__ __nv_bfloat16 g_Wqh[(size_t)DD * DD], g_Wql[(size_t)DD * DD];
__device__ __nv_bfloat16 g_Wkh[(size_t)DD * DD], g_Wkl[(size_t)DD * DD];
__device__ __nv_bfloat16 g_Woh[(size_t)DD * DD], g_Wol[(size_t)DD * DD];

// ============================================================================
// helpers
// ============================================================================
__device__ __forceinline__ uint32_t smem_u32(const void* p) {
    uint32_t a;
    asm("{ .reg .u64 t; cvta.to.shared.u64 t, %1; cvt.u32.u64 %0, t; }" : "=r"(a) : "l"(p));
    return a;
}

__device__ __forceinline__ void cp16(uint32_t s, const void* g) {
    asm volatile("cp.async.cg.shared.global [%0], [%1], 16;" :: "r"(s), "l"(g));
}

__device__ __forceinline__ uint32_t pack_bf16(__nv_bfloat16 a, __nv_bfloat16 b) {
    return (uint32_t)__bfloat16_as_ushort(a) | ((uint32_t)__bfloat16_as_ushort(b) << 16);
}

__device__ __forceinline__ void split1(float v, __nv_bfloat16& h, __nv_bfloat16& l) {
    h = __float2bfloat16_rn(v);
    l = __float2bfloat16_rn(v - __bfloat162float(h));
}

#define MMA_BF16(C, A0, A1, A2, A3, B0, B1) \
    asm volatile( \
        "mma.sync.aligned.m16n8k16.row.col.f32.bf16.bf16.f32 " \
        "{%0,%1,%2,%3}, {%4,%5,%6,%7}, {%8,%9}, {%0,%1,%2,%3};" \
        : "+f"((C)[0]), "+f"((C)[1]), "+f"((C)[2]), "+f"((C)[3]) \
        : "r"(A0), "r"(A1), "r"(A2), "r"(A3), "r"(B0), "r"(B1))

// ============================================================================
// fp32 -> bf16 hi/lo split (4 elements / thread)
// ============================================================================
__global__ __launch_bounds__(256) void cvt_split(
    const float* __restrict__ src,
    __nv_bfloat16* __restrict__ hi, __nv_bfloat16* __restrict__ lo)
{
    const size_t i4 = ((size_t)blockIdx.x * 256 + threadIdx.x) * 4;
    const float4 v = *(const float4*)(src + i4);
    __nv_bfloat16 h0, h1, h2, h3, l0, l1, l2, l3;
    split1(v.x, h0, l0); split1(v.y, h1, l1);
    split1(v.z, h2, l2); split1(v.w, h3, l3);
    uint2 ph, pl;
    ph.x = pack_bf16(h0, h1); ph.y = pack_bf16(h2, h3);
    pl.x = pack_bf16(l0, l1); pl.y = pack_bf16(l2, l3);
    *(uint2*)(hi + i4) = ph;
    *(uint2*)(lo + i4) = pl;
}

// ============================================================================
// bf16x3 GEMM, cp.async 2-stage pipeline: Y = A @ W^T + bias
// 512 thr / 16 warps, CTA 128x128, warp 32x32, K-chunk 64
// ============================================================================
#define GPITCH 80
#define PLANE_B (128 * GPITCH * 2)            // 20480
#define STAGE_B (4 * PLANE_B)                 // 81920
#define GEMM_SMEM (2 * STAGE_B)               // 163840

template<bool OUTF32>
__global__ void __launch_bounds__(512, 1) gemm_pre(
    const __nv_bfloat16* __restrict__ Ah_g, const __nv_bfloat16* __restrict__ Al_g,
    const __nv_bfloat16* __restrict__ Wh_g, const __nv_bfloat16* __restrict__ Wl_g,
    const float* __restrict__ bias,
    float* __restrict__ Y,
    __nv_bfloat16* __restrict__ Yh, __nv_bfloat16* __restrict__ Yl,
    int K, int N)
{
    extern __shared__ char sm[];
    const uint32_t sbase = smem_u32(sm);

    const int tid = threadIdx.x;
    const int lane = tid & 31;
    const int wid = tid >> 5;
    const int wy = wid >> 2;
    const int wx = wid & 3;
    const int m0 = blockIdx.y * 128;
    const int n0 = blockIdx.x * 128;

    const int srow = tid >> 2;
    const int sk0 = (tid & 3) << 4;
    const __nv_bfloat16* pAh = Ah_g + (size_t)(m0 + srow) * K + sk0;
    const __nv_bfloat16* pAl = Al_g + (size_t)(m0 + srow) * K + sk0;
    const __nv_bfloat16* pWh = Wh_g + (size_t)(n0 + srow) * K + sk0;
    const __nv_bfloat16* pWl = Wl_g + (size_t)(n0 + srow) * K + sk0;
    const uint32_t doff = (uint32_t)(srow * GPITCH + sk0) << 1;

    float acc[2][4][4];
#pragma unroll
    for (int t = 0; t < 2; t++)
#pragma unroll
        for (int u = 0; u < 4; u++)
#pragma unroll
            for (int i = 0; i < 4; i++) acc[t][u][i] = 0.f;

    const int r8 = lane >> 2;
    const int q2 = (lane & 3) << 1;
    const int nchunk = K >> 6;

    // stage issue
    auto issue = [&](int c) {
        const int kc = c << 6;
        const uint32_t dst = sbase + (uint32_t)(c & 1) * STAGE_B + doff;
        cp16(dst,                pAh + kc); cp16(dst + 16,                pAh + kc + 8);
        cp16(dst + PLANE_B,      pAl + kc); cp16(dst + PLANE_B + 16,      pAl + kc + 8);
        cp16(dst + 2 * PLANE_B,  pWh + kc); cp16(dst + 2 * PLANE_B + 16,  pWh + kc + 8);
        cp16(dst + 3 * PLANE_B,  pWl + kc); cp16(dst + 3 * PLANE_B + 16,  pWl + kc + 8);
        asm volatile("cp.async.commit_group;" ::: "memory");
    };

    issue(0);
    for (int c = 0; c < nchunk; c++) {
        if (c + 1 < nchunk) {
            issue(c + 1);
            asm volatile("cp.async.wait_group 1;" ::: "memory");
        } else {
            asm volatile("cp.async.wait_group 0;" ::: "memory");
        }
        __syncthreads();

        char* st = sm + (size_t)(c & 1) * STAGE_B;
        const __nv_bfloat16* Ah = (const __nv_bfloat16*)(st);
        const __nv_bfloat16* Al = (const __nv_bfloat16*)(st + PLANE_B);
        const __nv_bfloat16* Wh = (const __nv_bfloat16*)(st + 2 * PLANE_B);
        const __nv_bfloat16* Wl = (const __nv_bfloat16*)(st + 3 * PLANE_B);

#pragma unroll
        for (int ks = 0; ks < 4; ks++) {
            const int kk = ks << 4;
            uint32_t ahf[2][4], alf[2][4];
#pragma unroll
            for (int t = 0; t < 2; t++) {
                const int base = (wy * 32 + t * 16 + r8) * GPITCH + q2 + kk;
                ahf[t][0] = *(const uint32_t*)(Ah + base);
                ahf[t][1] = *(const uint32_t*)(Ah + base + 8 * GPITCH);
                ahf[t][2] = *(const uint32_t*)(Ah + base + 8);
                ahf[t][3] = *(const uint32_t*)(Ah + base + 8 * GPITCH + 8);
                alf[t][0] = *(const uint32_t*)(Al + base);
                alf[t][1] = *(const uint32_t*)(Al + base + 8 * GPITCH);
                alf[t][2] = *(const uint32_t*)(Al + base + 8);
                alf[t][3] = *(const uint32_t*)(Al + base + 8 * GPITCH + 8);
            }
#pragma unroll
            for (int u = 0; u < 4; u++) {
                const int nb = (wx * 32 + u * 8 + r8) * GPITCH + q2 + kk;
                const uint32_t bh0 = *(const uint32_t*)(Wh + nb);
                const uint32_t bh1 = *(const uint32_t*)(Wh + nb + 8);
                const uint32_t bl0 = *(const uint32_t*)(Wl + nb);
                const uint32_t bl1 = *(const uint32_t*)(Wl + nb + 8);
#pragma unroll
                for (int t = 0; t < 2; t++) {
                    MMA_BF16(acc[t][u], ahf[t][0], ahf[t][1], ahf[t][2], ahf[t][3], bh0, bh1);
                    MMA_BF16(acc[t][u], ahf[t][0], ahf[t][1], ahf[t][2], ahf[t][3], bl0, bl1);
                    MMA_BF16(acc[t][u], alf[t][0], alf[t][1], alf[t][2], alf[t][3], bh0, bh1);
                }
            }
        }
        __syncthreads();
    }

#pragma unroll
    for (int t = 0; t < 2; t++) {
        const int r0 = m0 + wy * 32 + t * 16 + r8;
#pragma unroll
        for (int u = 0; u < 4; u++) {
            const int col = n0 + wx * 32 + u * 8 + q2;
            const float b0 = bias[col], b1 = bias[col + 1];
            const float v00 = acc[t][u][0] + b0, v01 = acc[t][u][1] + b1;
            const float v10 = acc[t][u][2] + b0, v11 = acc[t][u][3] + b1;
            if (OUTF32) {
                *(float2*)(Y + (size_t)r0 * N + col) = make_float2(v00, v01);
                *(float2*)(Y + (size_t)(r0 + 8) * N + col) = make_float2(v10, v11);
            } else {
                __nv_bfloat16 h0, h1, l0, l1;
                split1(v00, h0, l0); split1(v01, h1, l1);
                *(uint32_t*)(Yh + (size_t)r0 * N + col) = pack_bf16(h0, h1);
                *(uint32_t*)(Yl + (size_t)r0 * N + col) = pack_bf16(l0, l1);
                split1(v10, h0, l0); split1(v11, h1, l1);
                *(uint32_t*)(Yh + (size_t)(r0 + 8) * N + col) = pack_bf16(h0, h1);
                *(uint32_t*)(Yl + (size_t)(r0 + 8) * N + col) = pack_bf16(l0, l1);
            }
        }
    }
}

// ============================================================================
// scores: S = (Q.K^T)*0.125 from pre-split planes, 128x128 causal tiles
// ============================================================================
#define SPITCH 72
#define SMAT_BYTES (128 * SPITCH * 2)         // 18432
#define SCORES_SMEM (4 * SMAT_BYTES)          // 73728

__global__ void __launch_bounds__(512, 1) scores_mma(void)
{
    int idx = blockIdx.x;
    int qt = 0;
    while ((qt + 1) * (qt + 2) / 2 <= idx) qt++;
    const int kt = idx - qt * (qt + 1) / 2;
    const int bh = blockIdx.y;
    const int b = bh >> 4;
    const int h = bh & 15;
    const int q0 = qt << 7;
    const int k0g = kt << 7;

    extern __shared__ char sm[];
    __nv_bfloat16* Qh = (__nv_bfloat16*)(sm);
    __nv_bfloat16* Ql = (__nv_bfloat16*)(sm + SMAT_BYTES);
    __nv_bfloat16* Kh = (__nv_bfloat16*)(sm + 2 * SMAT_BYTES);
    __nv_bfloat16* Kl = (__nv_bfloat16*)(sm + 3 * SMAT_BYTES);

    const int tid = threadIdx.x;
    const int lane = tid & 31;
    const int wid = tid >> 5;
    const int wy = wid >> 2;
    const int wx = wid & 3;

    {
        const int srow = tid >> 2;
        const int sk0 = (tid & 3) << 4;
        const size_t qoff = ((size_t)b * SS + q0 + srow) * DD + h * DK + sk0;
        const size_t koff = ((size_t)b * SS + k0g + srow) * DD + h * DK + sk0;
        const int sidx = srow * SPITCH + sk0;
        *(uint4*)(Qh + sidx)     = *(const uint4*)(g_Qh + qoff);
        *(uint4*)(Qh + sidx + 8) = *(const uint4*)(g_Qh + qoff + 8);
        *(uint4*)(Ql + sidx)     = *(const uint4*)(g_Ql + qoff);
        *(uint4*)(Ql + sidx + 8) = *(const uint4*)(g_Ql + qoff + 8);
        *(uint4*)(Kh + sidx)     = *(const uint4*)(g_Kh + koff);
        *(uint4*)(Kh + sidx + 8) = *(const uint4*)(g_Kh + koff + 8);
        *(uint4*)(Kl + sidx)     = *(const uint4*)(g_Kl + koff);
        *(uint4*)(Kl + sidx + 8) = *(const uint4*)(g_Kl + koff + 8);
    }
    __syncthreads();

    float acc[2][4][4];
#pragma unroll
    for (int t = 0; t < 2; t++)
#pragma unroll
        for (int u = 0; u < 4; u++)
#pragma unroll
            for (int i = 0; i < 4; i++) acc[t][u][i] = 0.f;

    const int r8 = lane >> 2;
    const int q2 = (lane & 3) << 1;

#pragma unroll
    for (int ks = 0; ks < 4; ks++) {
        const int kk = ks << 4;
        uint32_t ah[2][4], al[2][4];
#pragma unroll
        for (int t = 0; t < 2; t++) {
            const int base = (wy * 32 + t * 16 + r8) * SPITCH + q2 + kk;
            ah[t][0] = *(const uint32_t*)(Qh + base);
            ah[t][1] = *(const uint32_t*)(Qh + base + 8 * SPITCH);
            ah[t][2] = *(const uint32_t*)(Qh + base + 8);
            ah[t][3] = *(const uint32_t*)(Qh + base + 8 * SPITCH + 8);
            al[t][0] = *(const uint32_t*)(Ql + base);
            al[t][1] = *(const uint32_t*)(Ql + base + 8 * SPITCH);
            al[t][2] = *(const uint32_t*)(Ql + base + 8);
            al[t][3] = *(const uint32_t*)(Ql + base + 8 * SPITCH + 8);
        }
#pragma unroll
        for (int u = 0; u < 4; u++) {
            const int nb = (wx * 32 + u * 8 + r8) * SPITCH + q2 + kk;
            const uint32_t bh0 = *(const uint32_t*)(Kh + nb);
            const uint32_t bh1 = *(const uint32_t*)(Kh + nb + 8);
            const uint32_t bl0 = *(const uint32_t*)(Kl + nb);
            const uint32_t bl1 = *(const uint32_t*)(Kl + nb + 8);
#pragma unroll
            for (int t = 0; t < 2; t++) {
                MMA_BF16(acc[t][u], ah[t][0], ah[t][1], ah[t][2], ah[t][3], bh0, bh1);
                MMA_BF16(acc[t][u], ah[t][0], ah[t][1], ah[t][2], ah[t][3], bl0, bl1);
                MMA_BF16(acc[t][u], al[t][0], al[t][1], al[t][2], al[t][3], bh0, bh1);
            }
        }
    }

    const float scale = 0.125f;
#pragma unroll
    for (int t = 0; t < 2; t++) {
        const int r0 = q0 + wy * 32 + t * 16 + r8;
#pragma unroll
        for (int u = 0; u < 4; u++) {
            const int col = k0g + wx * 32 + u * 8 + q2;
            float2 v0, v1;
            v0.x = acc[t][u][0] * scale; v0.y = acc[t][u][1] * scale;
            v1.x = acc[t][u][2] * scale; v1.y = acc[t][u][3] * scale;
            *(float2*)(g_S + ((size_t)bh * SS + r0) * SS + col) = v0;
            *(float2*)(g_S + ((size_t)bh * SS + r0 + 8) * SS + col) = v1;
        }
    }
}

// ============================================================================
// fused softmax + AW: one block per (b,q), loops over 16 heads.
// Reads S (fp32), writes P as bf16 hi/lo planes (zero-filled to 128-boundary),
// and writes AW[b,q,:] = sum_h P[b,h,q,:].
// ============================================================================
__global__ __launch_bounds__(512) void softmax_aw(float* __restrict__ AW)
{
    const int q = blockIdx.x & (SS - 1);
    const int b = blockIdx.x >> 11;
    const int len = q + 1;
    const int bound = ((q >> 7) + 1) << 7;

    __shared__ float buf[SS];
    __shared__ float awr[SS];
    __shared__ float red[16];
    __shared__ float s_bcast;

    const int tid = threadIdx.x;
    const int lane = tid & 31, warp = tid >> 5;

    for (int k = tid; k < bound; k += 512) awr[k] = 0.f;
    __syncthreads();

    for (int h = 0; h < HH; h++) {
        const float* Srow = g_S + ((size_t)(b * HH + h) * SS + q) * SS;

        float m = -INFINITY;
        for (int k = tid; k < len; k += 512) {
            float v = Srow[k];
            buf[k] = v;
            m = fmaxf(m, v);
        }
#pragma unroll
        for (int o = 16; o; o >>= 1) m = fmaxf(m, __shfl_xor_sync(0xFFFFFFFFu, m, o));
        if (lane == 0) red[warp] = m;
        __syncthreads();
        if (tid == 0) {
            float t = red[0];
#pragma unroll
            for (int i = 1; i < 16; i++) t = fmaxf(t, red[i]);
            s_bcast = t;
        }
        __syncthreads();
        const float rowmax = s_bcast;
        __syncthreads();

        float s = 0.f;
        for (int k = tid; k < len; k += 512) {
            float e = __expf(buf[k] - rowmax);
            buf[k] = e;
            s += e;
        }
#pragma unroll
        for (int o = 16; o; o >>= 1) s += __shfl_xor_sync(0xFFFFFFFFu, s, o);
        if (lane == 0) red[warp] = s;
        __syncthreads();
        if (tid == 0) {
            float t = 0.f;
#pragma unroll
            for (int i = 0; i < 16; i++) t += red[i];
            s_bcast = t;
        }
        __syncthreads();
        const float inv = 1.0f / s_bcast;

        __nv_bfloat16* Ph = g_Ph + ((size_t)(b * HH + h) * SS + q) * SS;
        __nv_bfloat16* Pl = g_Pl + ((size_t)(b * HH + h) * SS + q) * SS;
        for (int k = tid; k < bound; k += 512) {
            const float v = (k < len) ? buf[k] * inv : 0.f;
            __nv_bfloat16 hh, ll;
            split1(v, hh, ll);
            Ph[k] = hh;
            Pl[k] = ll;
            awr[k] += v;
        }
        __syncthreads();
    }

    float* AWrow = AW + ((size_t)b * SS + q) * SS;
    for (int k = tid; k < SS; k += 512)
        AWrow[k] = (k < bound) ? awr[k] : 0.f;
}

// ============================================================================
// pv: C = P @ V (V = K planes); P read from pre-split planes; C -> bf16 planes
// CTA: (qt128, bh), 512 thr, warp tile 16x32
// ============================================================================
#define PV_PBYTES (128 * SPITCH * 2)
#define PV_VBYTES (64 * SPITCH * 2)
#define PV_SMEM (2 * PV_PBYTES + 2 * PV_VBYTES)  // 55296

__global__ void __launch_bounds__(512, 1) pv_mma(void)
{
    const int qt = blockIdx.x;
    const int bh = blockIdx.y;
    const int b = bh >> 4;
    const int h = bh & 15;
    const int q0 = qt << 7;

    extern __shared__ char sm[];
    __nv_bfloat16* Ph  = (__nv_bfloat16*)(sm);
    __nv_bfloat16* Pl  = (__nv_bfloat16*)(sm + PV_PBYTES);
    __nv_bfloat16* Vth = (__nv_bfloat16*)(sm + 2 * PV_PBYTES);
    __nv_bfloat16* Vtl = (__nv_bfloat16*)(sm + 2 * PV_PBYTES + PV_VBYTES);

    const int tid = threadIdx.x;
    const int lane = tid & 31;
    const int wid = tid >> 5;
    const int wy = wid >> 1;
    const int wx = wid & 1;

    const int r8 = lane >> 2;
    const int q2 = (lane & 3) << 1;

    float acc[4][4];
#pragma unroll
    for (int u = 0; u < 4; u++)
#pragma unroll
        for (int i = 0; i < 4; i++) acc[u][i] = 0.f;

    const int prow_s = tid >> 2;
    const int pk0 = (tid & 3) << 4;
    const int vrow_s = tid >> 3;
    const int vd0 = (tid & 7) << 3;

    const int nchunk = 2 * qt + 2;
    for (int kt = 0; kt < nchunk; kt++) {
        const int kc = kt << 6;
        const size_t poff = ((size_t)bh * SS + q0 + prow_s) * SS + kc + pk0;
        const uint4 ph0 = *(const uint4*)(g_Ph + poff);
        const uint4 ph1 = *(const uint4*)(g_Ph + poff + 8);
        const uint4 pl0 = *(const uint4*)(g_Pl + poff);
        const uint4 pl1 = *(const uint4*)(g_Pl + poff + 8);
        const size_t voff = ((size_t)b * SS + kc + vrow_s) * DD + h * DK + vd0;
        const uint4 vh = *(const uint4*)(g_Kh + voff);
        const uint4 vl = *(const uint4*)(g_Kl + voff);
        __syncthreads();
        {
            const int sidx = prow_s * SPITCH + pk0;
            *(uint4*)(Ph + sidx)     = ph0;
            *(uint4*)(Ph + sidx + 8) = ph1;
            *(uint4*)(Pl + sidx)     = pl0;
            *(uint4*)(Pl + sidx + 8) = pl1;
        }
        {
            const __nv_bfloat16* hv = (const __nv_bfloat16*)&vh;
            const __nv_bfloat16* lv = (const __nv_bfloat16*)&vl;
#pragma unroll
            for (int i = 0; i < 8; i++) {
                Vth[(vd0 + i) * SPITCH + vrow_s] = hv[i];
                Vtl[(vd0 + i) * SPITCH + vrow_s] = lv[i];
            }
        }
        __syncthreads();

#pragma unroll
        for (int ks = 0; ks < 4; ks++) {
            const int kk = ks << 4;
            uint32_t ah[4], al[4];
            {
                const int base = (wy * 16 + r8) * SPITCH + q2 + kk;
                ah[0] = *(const uint32_t*)(Ph + base);
                ah[1] = *(const uint32_t*)(Ph + base + 8 * SPITCH);
                ah[2] = *(const uint32_t*)(Ph + base + 8);
                ah[3] = *(const uint32_t*)(Ph + base + 8 * SPITCH + 8);
                al[0] = *(const uint32_t*)(Pl + base);
                al[1] = *(const uint32_t*)(Pl + base + 8 * SPITCH);
                al[2] = *(const uint32_t*)(Pl + base + 8);
                al[3] = *(const uint32_t*)(Pl + base + 8 * SPITCH + 8);
            }
#pragma unroll
            for (int u = 0; u < 4; u++) {
                const int nb = (wx * 32 + u * 8 + r8) * SPITCH + q2 + kk;
                const uint32_t bh0 = *(const uint32_t*)(Vth + nb);
                const uint32_t bh1 = *(const uint32_t*)(Vth + nb + 8);
                const uint32_t bl0 = *(const uint32_t*)(Vtl + nb);
                const uint32_t bl1 = *(const uint32_t*)(Vtl + nb + 8);
                MMA_BF16(acc[u], ah[0], ah[1], ah[2], ah[3], bh0, bh1);
                MMA_BF16(acc[u], ah[0], ah[1], ah[2], ah[3], bl0, bl1);
                MMA_BF16(acc[u], al[0], al[1], al[2], al[3], bh0, bh1);
            }
        }
    }

    // epilogue -> C bf16 hi/lo planes
    const int r0 = q0 + wy * 16 + r8;
#pragma unroll
    for (int u = 0; u < 4; u++) {
        const int d = wx * 32 + u * 8 + q2;
        const size_t o0 = ((size_t)b * SS + r0) * DD + h * DK + d;
        const size_t o1 = ((size_t)b * SS + r0 + 8) * DD + h * DK + d;
        __nv_bfloat16 h0, h1, l0, l1;
        split1(acc[u][0], h0, l0); split1(acc[u][1], h1, l1);
        *(uint32_t*)(g_Ch + o0) = pack_bf16(h0, h1);
        *(uint32_t*)(g_Cl + o0) = pack_bf16(l0, l1);
        split1(acc[u][2], h0, l0); split1(acc[u][3], h1, l1);
        *(uint32_t*)(g_Ch + o1) = pack_bf16(h0, h1);
        *(uint32_t*)(g_Cl + o1) = pack_bf16(l0, l1);
    }
}

// ============================================================================
// launch
// ============================================================================
extern "C" void kernel_launch(void* const* d_in, const int* in_sizes, int n_in,
                              void* d_out, int out_size)
{
    const float* x    = (const float*)d_in[0];
    const float* z    = (const float*)d_in[1];
    // d_in[2] = mask (causal tril; handled analytically)
    const float* wq_w = (const float*)d_in[3];
    const float* wq_b = (const float*)d_in[4];
    const float* wk_w = (const float*)d_in[5];
    const float* wk_b = (const float*)d_in[6];
    // d_in[7], d_in[8] = wv (dead param in reference: v uses wk)
    const float* wo_w = (const float*)d_in[9];
    const float* wo_b = (const float*)d_in[10];

    float* out = (float*)d_out;                              // [B,S,D]
    float* AW  = out + (size_t)BB * SS * DD;                 // [B,S,S]

    __nv_bfloat16 *pXh, *pXl, *pZh, *pZl, *pQh, *pQl, *pKh, *pKl, *pCh, *pCl;
    __nv_bfloat16 *pWqh, *pWql, *pWkh, *pWkl, *pWoh, *pWol;
    cudaGetSymbolAddress((void**)&pXh, g_Xh); cudaGetSymbolAddress((void**)&pXl, g_Xl);
    cudaGetSymbolAddress((void**)&pZh, g_Zh); cudaGetSymbolAddress((void**)&pZl, g_Zl);
    cudaGetSymbolAddress((void**)&pQh, g_Qh); cudaGetSymbolAddress((void**)&pQl, g_Ql);
    cudaGetSymbolAddress((void**)&pKh, g_Kh); cudaGetSymbolAddress((void**)&pKl, g_Kl);
    cudaGetSymbolAddress((void**)&pCh, g_Ch); cudaGetSymbolAddress((void**)&pCl, g_Cl);
    cudaGetSymbolAddress((void**)&pWqh, g_Wqh); cudaGetSymbolAddress((void**)&pWql, g_Wql);
    cudaGetSymbolAddress((void**)&pWkh, g_Wkh); cudaGetSymbolAddress((void**)&pWkl, g_Wkl);
    cudaGetSymbolAddress((void**)&pWoh, g_Woh); cudaGetSymbolAddress((void**)&pWol, g_Wol);

    static int smem_set = 0;
    if (!smem_set) {
        cudaFuncSetAttribute(gemm_pre<true>,  cudaFuncAttributeMaxDynamicSharedMemorySize, GEMM_SMEM);
        cudaFuncSetAttribute(gemm_pre<false>, cudaFuncAttributeMaxDynamicSharedMemorySize, GEMM_SMEM);
        cudaFuncSetAttribute(scores_mma, cudaFuncAttributeMaxDynamicSharedMemorySize, SCORES_SMEM);
        cudaFuncSetAttribute(pv_mma, cudaFuncAttributeMaxDynamicSharedMemorySize, PV_SMEM);
        smem_set = 1;
    }

    // split inputs + weights
    cvt_split<<<(MROWS * DD) / 1024, 256>>>(x, pXh, pXl);
    cvt_split<<<(MROWS * DD) / 1024, 256>>>(z, pZh, pZl);
    cvt_split<<<(DD * DD) / 1024, 256>>>(wq_w, pWqh, pWql);
    cvt_split<<<(DD * DD) / 1024, 256>>>(wk_w, pWkh, pWkl);
    cvt_split<<<(DD * DD) / 1024, 256>>>(wo_w, pWoh, pWol);

    const dim3 gProj(DD / 128, MROWS / 128);                 // (8,32)
    gemm_pre<false><<<gProj, 512, GEMM_SMEM>>>(pXh, pXl, pWqh, pWql, wq_b,
                                               nullptr, pQh, pQl, DD, DD);
    gemm_pre<false><<<gProj, 512, GEMM_SMEM>>>(pZh, pZl, pWkh, pWkl, wk_b,
                                               nullptr, pKh, pKl, DD, DD);

    scores_mma<<<dim3(136, BHT), 512, SCORES_SMEM>>>();

    softmax_aw<<<BB * SS, 512>>>(AW);

    pv_mma<<<dim3(16, BHT), 512, PV_SMEM>>>();

    gemm_pre<true><<<gProj, 512, GEMM_SMEM>>>(pCh, pCl, pWoh, pWol, wo_b,
                                              out, nullptr, nullptr, DD, DD);
}

// round 8
// speedup vs baseline: 1.1200x; 1.1200x over previous
#include <cuda_runtime.h>
#include <cuda_bf16.h>
#include <cstdint>
#include <math.h>

// Problem dims
#define BB 2
#define SS 2048
#define DD 1024
#define HH 16
#define DK 64
#define MROWS (BB * SS)   // 4096
#define BHT (BB * HH)     // 32

// -------- scratch (static __device__ globals; no allocation allowed) --------
__device__ float g_S[(size_t)BB * HH * SS * SS];                  // 512 MB raw scores (fp32)
__device__ __nv_bfloat16 g_Ph[(size_t)BB * HH * SS * SS];         // 256 MB P hi
__device__ __nv_bfloat16 g_Pl[(size_t)BB * HH * SS * SS];         // 256 MB P lo

// bf16 hi/lo planes
__device__ __nv_bfloat16 g_Xh[(size_t)MROWS * DD], g_Xl[(size_t)MROWS * DD];
__device__ __nv_bfloat16 g_Zh[(size_t)MROWS * DD], g_Zl[(size_t)MROWS * DD];
__device__ __nv_bfloat16 g_Qh[(size_t)MROWS * DD], g_Ql[(size_t)MROWS * DD];
__device__ __nv_bfloat16 g_Kh[(size_t)MROWS * DD], g_Kl[(size_t)MROWS * DD];
__device__ __nv_bfloat16 g_Ch[(size_t)MROWS * DD], g_Cl[(size_t)MROWS * DD];
__device__ __nv_bfloat16 g_Wqh[(size_t)DD * DD], g_Wql[(size_t)DD * DD];
__device__ __nv_bfloat16 g_Wkh[(size_t)DD * DD], g_Wkl[(size_t)DD * DD];
__device__ __nv_bfloat16 g_Woh[(size_t)DD * DD], g_Wol[(size_t)DD * DD];

// ============================================================================
// helpers
// ============================================================================
__device__ __forceinline__ uint32_t smem_u32(const void* p) {
    uint32_t a;
    asm("{ .reg .u64 t; cvta.to.shared.u64 t, %1; cvt.u32.u64 %0, t; }" : "=r"(a) : "l"(p));
    return a;
}

__device__ __forceinline__ uint32_t pack_bf16(__nv_bfloat16 a, __nv_bfloat16 b) {
    return (uint32_t)__bfloat16_as_ushort(a) | ((uint32_t)__bfloat16_as_ushort(b) << 16);
}

__device__ __forceinline__ void split1(float v, __nv_bfloat16& h, __nv_bfloat16& l) {
    h = __float2bfloat16_rn(v);
    l = __float2bfloat16_rn(v - __bfloat162float(h));
}

#define MMA_BF16(C, A0, A1, A2, A3, B0, B1) \
    asm volatile( \
        "mma.sync.aligned.m16n8k16.row.col.f32.bf16.bf16.f32 " \
        "{%0,%1,%2,%3}, {%4,%5,%6,%7}, {%8,%9}, {%0,%1,%2,%3};" \
        : "+f"((C)[0]), "+f"((C)[1]), "+f"((C)[2]), "+f"((C)[3]) \
        : "r"(A0), "r"(A1), "r"(A2), "r"(A3), "r"(B0), "r"(B1))

__device__ __forceinline__ void ldsm4(uint32_t* r, uint32_t addr) {
    asm volatile("ldmatrix.sync.aligned.m8n8.x4.shared.b16 {%0,%1,%2,%3}, [%4];"
        : "=r"(r[0]), "=r"(r[1]), "=r"(r[2]), "=r"(r[3]) : "r"(addr));
}
__device__ __forceinline__ void ldsm4t(uint32_t* r, uint32_t addr) {
    asm volatile("ldmatrix.sync.aligned.m8n8.x4.trans.shared.b16 {%0,%1,%2,%3}, [%4];"
        : "=r"(r[0]), "=r"(r[1]), "=r"(r[2]), "=r"(r[3]) : "r"(addr));
}

// shared-memory pitch (bf16 elements): 72 -> 144B rows -> conflict-free LDSM
#define GP 72
#define PLANE (128 * GP * 2)          // 18432 bytes per 128-row plane
#define TOFF  (16 * GP * 2)           // byte offset of 16 rows = 2304

// ============================================================================
// fp32 -> bf16 hi/lo split (4 elements / thread)
// ============================================================================
__global__ __launch_bounds__(256) void cvt_split(
    const float* __restrict__ src,
    __nv_bfloat16* __restrict__ hi, __nv_bfloat16* __restrict__ lo)
{
    const size_t i4 = ((size_t)blockIdx.x * 256 + threadIdx.x) * 4;
    const float4 v = *(const float4*)(src + i4);
    __nv_bfloat16 h0, h1, h2, h3, l0, l1, l2, l3;
    split1(v.x, h0, l0); split1(v.y, h1, l1);
    split1(v.z, h2, l2); split1(v.w, h3, l3);
    uint2 ph, pl;
    ph.x = pack_bf16(h0, h1); ph.y = pack_bf16(h2, h3);
    pl.x = pack_bf16(l0, l1); pl.y = pack_bf16(l2, l3);
    *(uint2*)(hi + i4) = ph;
    *(uint2*)(lo + i4) = pl;
}

// ============================================================================
// bf16x3 GEMM (ldmatrix fragments): Y = A @ W^T + bias
// 512 thr / 16 warps, CTA 128x128, warp 32x32, K-chunk 64
// smem: Ah | Al | Wh | Wl, each 128 x 64 @ pitch 72
// ============================================================================
#define GEMM_SMEM (4 * PLANE)         // 73728

template<bool OUTF32>
__global__ void __launch_bounds__(512, 1) gemm_pre(
    const __nv_bfloat16* __restrict__ Ah_g, const __nv_bfloat16* __restrict__ Al_g,
    const __nv_bfloat16* __restrict__ Wh_g, const __nv_bfloat16* __restrict__ Wl_g,
    const float* __restrict__ bias,
    float* __restrict__ Y,
    __nv_bfloat16* __restrict__ Yh, __nv_bfloat16* __restrict__ Yl,
    int K, int N)
{
    extern __shared__ char sm[];
    const uint32_t sb = smem_u32(sm);
    __nv_bfloat16* smAh = (__nv_bfloat16*)(sm);
    __nv_bfloat16* smAl = (__nv_bfloat16*)(sm + PLANE);
    __nv_bfloat16* smWh = (__nv_bfloat16*)(sm + 2 * PLANE);
    __nv_bfloat16* smWl = (__nv_bfloat16*)(sm + 3 * PLANE);

    const int tid = threadIdx.x;
    const int lane = tid & 31;
    const int wid = tid >> 5;
    const int wy = wid >> 2;
    const int wx = wid & 3;
    const int m0 = blockIdx.y * 128;
    const int n0 = blockIdx.x * 128;

    const int srow = tid >> 2;
    const int sk0 = (tid & 3) << 4;
    const __nv_bfloat16* pAh = Ah_g + (size_t)(m0 + srow) * K + sk0;
    const __nv_bfloat16* pAl = Al_g + (size_t)(m0 + srow) * K + sk0;
    const __nv_bfloat16* pWh = Wh_g + (size_t)(n0 + srow) * K + sk0;
    const __nv_bfloat16* pWl = Wl_g + (size_t)(n0 + srow) * K + sk0;
    const int sidx = srow * GP + sk0;

    // ldmatrix lane address components
    const int lr = lane & 7;
    const int lm01 = (lane >> 3) & 1;
    const int lm23 = lane >> 4;
    // A (row-major, K-major frags): m0/m1 pick +8 rows, m2/m3 pick +8 cols
    const uint32_t aA = sb + (uint32_t)((((wy * 32 + lm01 * 8 + lr) * GP) + lm23 * 8) << 1);
    // B (n-rows, K-major): m0/m1 pick +8 cols, m2/m3 pick +8 n-rows
    const uint32_t aW = sb + 2 * PLANE +
        (uint32_t)((((wx * 32 + lm23 * 8 + lr) * GP) + lm01 * 8) << 1);

    float acc[2][4][4];
#pragma unroll
    for (int t = 0; t < 2; t++)
#pragma unroll
        for (int u = 0; u < 4; u++)
#pragma unroll
            for (int i = 0; i < 4; i++) acc[t][u][i] = 0.f;

    const int r8 = lane >> 2;
    const int q2 = (lane & 3) << 1;
    const int nchunk = K >> 6;

    for (int c = 0; c < nchunk; c++) {
        const int kc = c << 6;
        const uint4 ah0 = *(const uint4*)(pAh + kc);
        const uint4 ah1 = *(const uint4*)(pAh + kc + 8);
        const uint4 al0 = *(const uint4*)(pAl + kc);
        const uint4 al1 = *(const uint4*)(pAl + kc + 8);
        const uint4 wh0 = *(const uint4*)(pWh + kc);
        const uint4 wh1 = *(const uint4*)(pWh + kc + 8);
        const uint4 wl0 = *(const uint4*)(pWl + kc);
        const uint4 wl1 = *(const uint4*)(pWl + kc + 8);
        __syncthreads();
        *(uint4*)(smAh + sidx)     = ah0; *(uint4*)(smAh + sidx + 8) = ah1;
        *(uint4*)(smAl + sidx)     = al0; *(uint4*)(smAl + sidx + 8) = al1;
        *(uint4*)(smWh + sidx)     = wh0; *(uint4*)(smWh + sidx + 8) = wh1;
        *(uint4*)(smWl + sidx)     = wl0; *(uint4*)(smWl + sidx + 8) = wl1;
        __syncthreads();

#pragma unroll
        for (int ks = 0; ks < 4; ks++) {
            const uint32_t kb = (uint32_t)ks << 5;    // 16 elems * 2B
            uint32_t ahf[2][4], alf[2][4];
            ldsm4(ahf[0], aA + kb);
            ldsm4(ahf[1], aA + TOFF + kb);
            ldsm4(alf[0], aA + PLANE + kb);
            ldsm4(alf[1], aA + PLANE + TOFF + kb);
            uint32_t bhf[4][2], blf[4][2], tmp[4];
            ldsm4(tmp, aW + kb);
            bhf[0][0] = tmp[0]; bhf[0][1] = tmp[1]; bhf[1][0] = tmp[2]; bhf[1][1] = tmp[3];
            ldsm4(tmp, aW + TOFF + kb);
            bhf[2][0] = tmp[0]; bhf[2][1] = tmp[1]; bhf[3][0] = tmp[2]; bhf[3][1] = tmp[3];
            ldsm4(tmp, aW + PLANE + kb);
            blf[0][0] = tmp[0]; blf[0][1] = tmp[1]; blf[1][0] = tmp[2]; blf[1][1] = tmp[3];
            ldsm4(tmp, aW + PLANE + TOFF + kb);
            blf[2][0] = tmp[0]; blf[2][1] = tmp[1]; blf[3][0] = tmp[2]; blf[3][1] = tmp[3];
#pragma unroll
            for (int u = 0; u < 4; u++) {
#pragma unroll
                for (int t = 0; t < 2; t++) {
                    MMA_BF16(acc[t][u], ahf[t][0], ahf[t][1], ahf[t][2], ahf[t][3],
                             bhf[u][0], bhf[u][1]);
                    MMA_BF16(acc[t][u], ahf[t][0], ahf[t][1], ahf[t][2], ahf[t][3],
                             blf[u][0], blf[u][1]);
                    MMA_BF16(acc[t][u], alf[t][0], alf[t][1], alf[t][2], alf[t][3],
                             bhf[u][0], bhf[u][1]);
                }
            }
        }
        __syncthreads();
    }

#pragma unroll
    for (int t = 0; t < 2; t++) {
        const int r0 = m0 + wy * 32 + t * 16 + r8;
#pragma unroll
        for (int u = 0; u < 4; u++) {
            const int col = n0 + wx * 32 + u * 8 + q2;
            const float b0 = bias[col], b1 = bias[col + 1];
            const float v00 = acc[t][u][0] + b0, v01 = acc[t][u][1] + b1;
            const float v10 = acc[t][u][2] + b0, v11 = acc[t][u][3] + b1;
            if (OUTF32) {
                *(float2*)(Y + (size_t)r0 * N + col) = make_float2(v00, v01);
                *(float2*)(Y + (size_t)(r0 + 8) * N + col) = make_float2(v10, v11);
            } else {
                __nv_bfloat16 h0, h1, l0, l1;
                split1(v00, h0, l0); split1(v01, h1, l1);
                *(uint32_t*)(Yh + (size_t)r0 * N + col) = pack_bf16(h0, h1);
                *(uint32_t*)(Yl + (size_t)r0 * N + col) = pack_bf16(l0, l1);
                split1(v10, h0, l0); split1(v11, h1, l1);
                *(uint32_t*)(Yh + (size_t)(r0 + 8) * N + col) = pack_bf16(h0, h1);
                *(uint32_t*)(Yl + (size_t)(r0 + 8) * N + col) = pack_bf16(l0, l1);
            }
        }
    }
}

// ============================================================================
// scores: S = (Q.K^T)*0.125, 128x128 causal tiles, ldmatrix fragments
// ============================================================================
#define SCORES_SMEM (4 * PLANE)       // 73728

__global__ void __launch_bounds__(512, 1) scores_mma(void)
{
    int idx = blockIdx.x;
    int qt = 0;
    while ((qt + 1) * (qt + 2) / 2 <= idx) qt++;
    const int kt = idx - qt * (qt + 1) / 2;
    const int bh = blockIdx.y;
    const int b = bh >> 4;
    const int h = bh & 15;
    const int q0 = qt << 7;
    const int k0g = kt << 7;

    extern __shared__ char sm[];
    const uint32_t sb = smem_u32(sm);
    __nv_bfloat16* Qh = (__nv_bfloat16*)(sm);
    __nv_bfloat16* Ql = (__nv_bfloat16*)(sm + PLANE);
    __nv_bfloat16* Kh = (__nv_bfloat16*)(sm + 2 * PLANE);
    __nv_bfloat16* Kl = (__nv_bfloat16*)(sm + 3 * PLANE);

    const int tid = threadIdx.x;
    const int lane = tid & 31;
    const int wid = tid >> 5;
    const int wy = wid >> 2;
    const int wx = wid & 3;

    {
        const int srow = tid >> 2;
        const int sk0 = (tid & 3) << 4;
        const size_t qoff = ((size_t)b * SS + q0 + srow) * DD + h * DK + sk0;
        const size_t koff = ((size_t)b * SS + k0g + srow) * DD + h * DK + sk0;
        const int sidx = srow * GP + sk0;
        *(uint4*)(Qh + sidx)     = *(const uint4*)(g_Qh + qoff);
        *(uint4*)(Qh + sidx + 8) = *(const uint4*)(g_Qh + qoff + 8);
        *(uint4*)(Ql + sidx)     = *(const uint4*)(g_Ql + qoff);
        *(uint4*)(Ql + sidx + 8) = *(const uint4*)(g_Ql + qoff + 8);
        *(uint4*)(Kh + sidx)     = *(const uint4*)(g_Kh + koff);
        *(uint4*)(Kh + sidx + 8) = *(const uint4*)(g_Kh + koff + 8);
        *(uint4*)(Kl + sidx)     = *(const uint4*)(g_Kl + koff);
        *(uint4*)(Kl + sidx + 8) = *(const uint4*)(g_Kl + koff + 8);
    }
    __syncthreads();

    const int lr = lane & 7;
    const int lm01 = (lane >> 3) & 1;
    const int lm23 = lane >> 4;
    const uint32_t aQ = sb + (uint32_t)((((wy * 32 + lm01 * 8 + lr) * GP) + lm23 * 8) << 1);
    const uint32_t aK = sb + 2 * PLANE +
        (uint32_t)((((wx * 32 + lm23 * 8 + lr) * GP) + lm01 * 8) << 1);

    float acc[2][4][4];
#pragma unroll
    for (int t = 0; t < 2; t++)
#pragma unroll
        for (int u = 0; u < 4; u++)
#pragma unroll
            for (int i = 0; i < 4; i++) acc[t][u][i] = 0.f;

    const int r8 = lane >> 2;
    const int q2 = (lane & 3) << 1;

#pragma unroll
    for (int ks = 0; ks < 4; ks++) {
        const uint32_t kb = (uint32_t)ks << 5;
        uint32_t ahf[2][4], alf[2][4];
        ldsm4(ahf[0], aQ + kb);
        ldsm4(ahf[1], aQ + TOFF + kb);
        ldsm4(alf[0], aQ + PLANE + kb);
        ldsm4(alf[1], aQ + PLANE + TOFF + kb);
        uint32_t bhf[4][2], blf[4][2], tmp[4];
        ldsm4(tmp, aK + kb);
        bhf[0][0] = tmp[0]; bhf[0][1] = tmp[1]; bhf[1][0] = tmp[2]; bhf[1][1] = tmp[3];
        ldsm4(tmp, aK + TOFF + kb);
        bhf[2][0] = tmp[0]; bhf[2][1] = tmp[1]; bhf[3][0] = tmp[2]; bhf[3][1] = tmp[3];
        ldsm4(tmp, aK + PLANE + kb);
        blf[0][0] = tmp[0]; blf[0][1] = tmp[1]; blf[1][0] = tmp[2]; blf[1][1] = tmp[3];
        ldsm4(tmp, aK + PLANE + TOFF + kb);
        blf[2][0] = tmp[0]; blf[2][1] = tmp[1]; blf[3][0] = tmp[2]; blf[3][1] = tmp[3];
#pragma unroll
        for (int u = 0; u < 4; u++) {
#pragma unroll
            for (int t = 0; t < 2; t++) {
                MMA_BF16(acc[t][u], ahf[t][0], ahf[t][1], ahf[t][2], ahf[t][3],
                         bhf[u][0], bhf[u][1]);
                MMA_BF16(acc[t][u], ahf[t][0], ahf[t][1], ahf[t][2], ahf[t][3],
                         blf[u][0], blf[u][1]);
                MMA_BF16(acc[t][u], alf[t][0], alf[t][1], alf[t][2], alf[t][3],
                         bhf[u][0], bhf[u][1]);
            }
        }
    }

    const float scale = 0.125f;
#pragma unroll
    for (int t = 0; t < 2; t++) {
        const int r0 = q0 + wy * 32 + t * 16 + r8;
#pragma unroll
        for (int u = 0; u < 4; u++) {
            const int col = k0g + wx * 32 + u * 8 + q2;
            float2 v0, v1;
            v0.x = acc[t][u][0] * scale; v0.y = acc[t][u][1] * scale;
            v1.x = acc[t][u][2] * scale; v1.y = acc[t][u][3] * scale;
            *(float2*)(g_S + ((size_t)bh * SS + r0) * SS + col) = v0;
            *(float2*)(g_S + ((size_t)bh * SS + r0 + 8) * SS + col) = v1;
        }
    }
}

// ============================================================================
// fused softmax + AW: one block per (b,q), loops over 16 heads.
// Reads S (fp32), writes P as bf16 hi/lo planes, writes AW.
// ============================================================================
__global__ __launch_bounds__(512) void softmax_aw(float* __restrict__ AW)
{
    const int q = blockIdx.x & (SS - 1);
    const int b = blockIdx.x >> 11;
    const int len = q + 1;
    const int bound = ((q >> 7) + 1) << 7;

    __shared__ float buf[SS];
    __shared__ float awr[SS];
    __shared__ float red[16];
    __shared__ float s_bcast;

    const int tid = threadIdx.x;
    const int lane = tid & 31, warp = tid >> 5;

    for (int k = tid; k < bound; k += 512) awr[k] = 0.f;
    __syncthreads();

    for (int h = 0; h < HH; h++) {
        const float* Srow = g_S + ((size_t)(b * HH + h) * SS + q) * SS;

        float m = -INFINITY;
        for (int k = tid; k < len; k += 512) {
            float v = Srow[k];
            buf[k] = v;
            m = fmaxf(m, v);
        }
#pragma unroll
        for (int o = 16; o; o >>= 1) m = fmaxf(m, __shfl_xor_sync(0xFFFFFFFFu, m, o));
        if (lane == 0) red[warp] = m;
        __syncthreads();
        if (tid == 0) {
            float t = red[0];
#pragma unroll
            for (int i = 1; i < 16; i++) t = fmaxf(t, red[i]);
            s_bcast = t;
        }
        __syncthreads();
        const float rowmax = s_bcast;
        __syncthreads();

        float s = 0.f;
        for (int k = tid; k < len; k += 512) {
            float e = __expf(buf[k] - rowmax);
            buf[k] = e;
            s += e;
        }
#pragma unroll
        for (int o = 16; o; o >>= 1) s += __shfl_xor_sync(0xFFFFFFFFu, s, o);
        if (lane == 0) red[warp] = s;
        __syncthreads();
        if (tid == 0) {
            float t = 0.f;
#pragma unroll
            for (int i = 0; i < 16; i++) t += red[i];
            s_bcast = t;
        }
        __syncthreads();
        const float inv = 1.0f / s_bcast;

        __nv_bfloat16* Ph = g_Ph + ((size_t)(b * HH + h) * SS + q) * SS;
        __nv_bfloat16* Pl = g_Pl + ((size_t)(b * HH + h) * SS + q) * SS;
        for (int k = tid; k < bound; k += 512) {
            const float v = (k < len) ? buf[k] * inv : 0.f;
            __nv_bfloat16 hh, ll;
            split1(v, hh, ll);
            Ph[k] = hh;
            Pl[k] = ll;
            awr[k] += v;
        }
        __syncthreads();
    }

    float* AWrow = AW + ((size_t)b * SS + q) * SS;
    for (int k = tid; k < SS; k += 512)
        AWrow[k] = (k < bound) ? awr[k] : 0.f;
}

// ============================================================================
// pv: C = P @ V (V = K planes), ldmatrix frags, V via ldmatrix.trans (K-major)
// CTA: (qt128, bh), 512 thr, warp tile 16x32
// smem: Ph | Pl (128x64 @72) ; Vh | Vl (64x64 @72, K-major)
// ============================================================================
#define VPLANE (64 * GP * 2)                  // 9216
#define PV_SMEM (2 * PLANE + 2 * VPLANE)      // 55296

__global__ void __launch_bounds__(512, 1) pv_mma(void)
{
    const int qt = blockIdx.x;
    const int bh = blockIdx.y;
    const int b = bh >> 4;
    const int h = bh & 15;
    const int q0 = qt << 7;

    extern __shared__ char sm[];
    const uint32_t sb = smem_u32(sm);
    __nv_bfloat16* Ph = (__nv_bfloat16*)(sm);
    __nv_bfloat16* Pl = (__nv_bfloat16*)(sm + PLANE);
    __nv_bfloat16* Vh = (__nv_bfloat16*)(sm + 2 * PLANE);
    __nv_bfloat16* Vl = (__nv_bfloat16*)(sm + 2 * PLANE + VPLANE);

    const int tid = threadIdx.x;
    const int lane = tid & 31;
    const int wid = tid >> 5;
    const int wy = wid >> 1;                  // 0..7 -> 16 rows each
    const int wx = wid & 1;                   // 0..1 -> 32 cols each

    const int lr = lane & 7;
    const int lm01 = (lane >> 3) & 1;
    const int lm23 = lane >> 4;
    // A (P): rows q, cols k
    const uint32_t aP = sb + (uint32_t)((((wy * 16 + lm01 * 8 + lr) * GP) + lm23 * 8) << 1);
    // B (V, K-major storage, trans load): rows k, cols d
    const uint32_t aV = sb + 2 * PLANE +
        (uint32_t)((((lm01 * 8 + lr) * GP) + wx * 32 + lm23 * 8) << 1);

    const int r8 = lane >> 2;
    const int q2 = (lane & 3) << 1;

    float acc[4][4];
#pragma unroll
    for (int u = 0; u < 4; u++)
#pragma unroll
        for (int i = 0; i < 4; i++) acc[u][i] = 0.f;

    const int prow_s = tid >> 2;              // 0..127
    const int pk0 = (tid & 3) << 4;           // 0,16,32,48
    const int krow = tid >> 3;                // 0..63
    const int vd0 = (tid & 7) << 3;           // 0..56

    const int nchunk = 2 * qt + 2;
    for (int kt = 0; kt < nchunk; kt++) {
        const int kc = kt << 6;
        const size_t poff = ((size_t)bh * SS + q0 + prow_s) * SS + kc + pk0;
        const uint4 ph0 = *(const uint4*)(g_Ph + poff);
        const uint4 ph1 = *(const uint4*)(g_Ph + poff + 8);
        const uint4 pl0 = *(const uint4*)(g_Pl + poff);
        const uint4 pl1 = *(const uint4*)(g_Pl + poff + 8);
        const size_t voff = ((size_t)b * SS + kc + krow) * DD + h * DK + vd0;
        const uint4 vh = *(const uint4*)(g_Kh + voff);
        const uint4 vl = *(const uint4*)(g_Kl + voff);
        __syncthreads();
        {
            const int sidx = prow_s * GP + pk0;
            *(uint4*)(Ph + sidx)     = ph0;
            *(uint4*)(Ph + sidx + 8) = ph1;
            *(uint4*)(Pl + sidx)     = pl0;
            *(uint4*)(Pl + sidx + 8) = pl1;
            const int vidx = krow * GP + vd0;
            *(uint4*)(Vh + vidx) = vh;
            *(uint4*)(Vl + vidx) = vl;
        }
        __syncthreads();

#pragma unroll
        for (int ks = 0; ks < 4; ks++) {
            const uint32_t kb = (uint32_t)ks << 5;         // P col offset (bytes)
            const uint32_t vkb = (uint32_t)ks * TOFF;      // V row offset (16 k-rows)
            uint32_t ahf[4], alf[4];
            ldsm4(ahf, aP + kb);
            ldsm4(alf, aP + PLANE + kb);
            uint32_t bhf[4][2], blf[4][2], tmp[4];
            ldsm4t(tmp, aV + vkb);
            bhf[0][0] = tmp[0]; bhf[0][1] = tmp[1]; bhf[1][0] = tmp[2]; bhf[1][1] = tmp[3];
            ldsm4t(tmp, aV + vkb + 32);                    // +16 d elements
            bhf[2][0] = tmp[0]; bhf[2][1] = tmp[1]; bhf[3][0] = tmp[2]; bhf[3][1] = tmp[3];
            ldsm4t(tmp, aV + VPLANE + vkb);
            blf[0][0] = tmp[0]; blf[0][1] = tmp[1]; blf[1][0] = tmp[2]; blf[1][1] = tmp[3];
            ldsm4t(tmp, aV + VPLANE + vkb + 32);
            blf[2][0] = tmp[0]; blf[2][1] = tmp[1]; blf[3][0] = tmp[2]; blf[3][1] = tmp[3];
#pragma unroll
            for (int u = 0; u < 4; u++) {
                MMA_BF16(acc[u], ahf[0], ahf[1], ahf[2], ahf[3], bhf[u][0], bhf[u][1]);
                MMA_BF16(acc[u], ahf[0], ahf[1], ahf[2], ahf[3], blf[u][0], blf[u][1]);
                MMA_BF16(acc[u], alf[0], alf[1], alf[2], alf[3], bhf[u][0], bhf[u][1]);
            }
        }
    }

    // epilogue -> C bf16 hi/lo planes
    const int r0 = q0 + wy * 16 + r8;
#pragma unroll
    for (int u = 0; u < 4; u++) {
        const int d = wx * 32 + u * 8 + q2;
        const size_t o0 = ((size_t)b * SS + r0) * DD + h * DK + d;
        const size_t o1 = ((size_t)b * SS + r0 + 8) * DD + h * DK + d;
        __nv_bfloat16 h0, h1, l0, l1;
        split1(acc[u][0], h0, l0); split1(acc[u][1], h1, l1);
        *(uint32_t*)(g_Ch + o0) = pack_bf16(h0, h1);
        *(uint32_t*)(g_Cl + o0) = pack_bf16(l0, l1);
        split1(acc[u][2], h0, l0); split1(acc[u][3], h1, l1);
        *(uint32_t*)(g_Ch + o1) = pack_bf16(h0, h1);
        *(uint32_t*)(g_Cl + o1) = pack_bf16(l0, l1);
    }
}

// ============================================================================
// launch
// ============================================================================
extern "C" void kernel_launch(void* const* d_in, const int* in_sizes, int n_in,
                              void* d_out, int out_size)
{
    const float* x    = (const float*)d_in[0];
    const float* z    = (const float*)d_in[1];
    // d_in[2] = mask (causal tril; handled analytically)
    const float* wq_w = (const float*)d_in[3];
    const float* wq_b = (const float*)d_in[4];
    const float* wk_w = (const float*)d_in[5];
    const float* wk_b = (const float*)d_in[6];
    // d_in[7], d_in[8] = wv (dead param in reference: v uses wk)
    const float* wo_w = (const float*)d_in[9];
    const float* wo_b = (const float*)d_in[10];

    float* out = (float*)d_out;                              // [B,S,D]
    float* AW  = out + (size_t)BB * SS * DD;                 // [B,S,S]

    __nv_bfloat16 *pXh, *pXl, *pZh, *pZl, *pQh, *pQl, *pKh, *pKl, *pCh, *pCl;
    __nv_bfloat16 *pWqh, *pWql, *pWkh, *pWkl, *pWoh, *pWol;
    cudaGetSymbolAddress((void**)&pXh, g_Xh); cudaGetSymbolAddress((void**)&pXl, g_Xl);
    cudaGetSymbolAddress((void**)&pZh, g_Zh); cudaGetSymbolAddress((void**)&pZl, g_Zl);
    cudaGetSymbolAddress((void**)&pQh, g_Qh); cudaGetSymbolAddress((void**)&pQl, g_Ql);
    cudaGetSymbolAddress((void**)&pKh, g_Kh); cudaGetSymbolAddress((void**)&pKl, g_Kl);
    cudaGetSymbolAddress((void**)&pCh, g_Ch); cudaGetSymbolAddress((void**)&pCl, g_Cl);
    cudaGetSymbolAddress((void**)&pWqh, g_Wqh); cudaGetSymbolAddress((void**)&pWql, g_Wql);
    cudaGetSymbolAddress((void**)&pWkh, g_Wkh); cudaGetSymbolAddress((void**)&pWkl, g_Wkl);
    cudaGetSymbolAddress((void**)&pWoh, g_Woh); cudaGetSymbolAddress((void**)&pWol, g_Wol);

    static int smem_set = 0;
    if (!smem_set) {
        cudaFuncSetAttribute(gemm_pre<true>,  cudaFuncAttributeMaxDynamicSharedMemorySize, GEMM_SMEM);
        cudaFuncSetAttribute(gemm_pre<false>, cudaFuncAttributeMaxDynamicSharedMemorySize, GEMM_SMEM);
        cudaFuncSetAttribute(scores_mma, cudaFuncAttributeMaxDynamicSharedMemorySize, SCORES_SMEM);
        cudaFuncSetAttribute(pv_mma, cudaFuncAttributeMaxDynamicSharedMemorySize, PV_SMEM);
        smem_set = 1;
    }

    // split inputs + weights
    cvt_split<<<(MROWS * DD) / 1024, 256>>>(x, pXh, pXl);
    cvt_split<<<(MROWS * DD) / 1024, 256>>>(z, pZh, pZl);
    cvt_split<<<(DD * DD) / 1024, 256>>>(wq_w, pWqh, pWql);
    cvt_split<<<(DD * DD) / 1024, 256>>>(wk_w, pWkh, pWkl);
    cvt_split<<<(DD * DD) / 1024, 256>>>(wo_w, pWoh, pWol);

    const dim3 gProj(DD / 128, MROWS / 128);                 // (8,32)
    gemm_pre<false><<<gProj, 512, GEMM_SMEM>>>(pXh, pXl, pWqh, pWql, wq_b,
                                               nullptr, pQh, pQl, DD, DD);
    gemm_pre<false><<<gProj, 512, GEMM_SMEM>>>(pZh, pZl, pWkh, pWkl, wk_b,
                                               nullptr, pKh, pKl, DD, DD);

    scores_mma<<<dim3(136, BHT), 512, SCORES_SMEM>>>();

    softmax_aw<<<BB * SS, 512>>>(AW);

    pv_mma<<<dim3(16, BHT), 512, PV_SMEM>>>();

    gemm_pre<true><<<gProj, 512, GEMM_SMEM>>>(pCh, pCl, pWoh, pWol, wo_b,
                                              out, nullptr, nullptr, DD, DD);
}

// round 10
// speedup vs baseline: 1.2479x; 1.1141x over previous
#include <cuda_runtime.h>
#include <cuda_bf16.h>
#include <cstdint>
#include <math.h>

// Problem dims
#define BB 2
#define SS 2048
#define DD 1024
#define HH 16
#define DK 64
#define MROWS (BB * SS)   // 4096
#define BHT (BB * HH)     // 32

// -------- scratch (static __device__ globals; no allocation allowed) --------
__device__ float g_S[(size_t)BB * HH * SS * SS];                  // 512 MB raw scores (fp32)
__device__ __nv_bfloat16 g_Ph[(size_t)BB * HH * SS * SS];         // 256 MB P hi
__device__ __nv_bfloat16 g_Pl[(size_t)BB * HH * SS * SS];         // 256 MB P lo

// bf16 hi/lo planes
__device__ __nv_bfloat16 g_Xh[(size_t)MROWS * DD], g_Xl[(size_t)MROWS * DD];
__device__ __nv_bfloat16 g_Zh[(size_t)MROWS * DD], g_Zl[(size_t)MROWS * DD];
__device__ __nv_bfloat16 g_Qh[(size_t)MROWS * DD], g_Ql[(size_t)MROWS * DD];
__device__ __nv_bfloat16 g_Kh[(size_t)MROWS * DD], g_Kl[(size_t)MROWS * DD];
__device__ __nv_bfloat16 g_Ch[(size_t)MROWS * DD], g_Cl[(size_t)MROWS * DD];
__device__ __nv_bfloat16 g_Wqh[(size_t)DD * DD], g_Wql[(size_t)DD * DD];
__device__ __nv_bfloat16 g_Wkh[(size_t)DD * DD], g_Wkl[(size_t)DD * DD];
__device__ __nv_bfloat16 g_Woh[(size_t)DD * DD], g_Wol[(size_t)DD * DD];

// ============================================================================
// helpers
// ============================================================================
__device__ __forceinline__ uint32_t smem_u32(const void* p) {
    uint32_t a;
    asm("{ .reg .u64 t; cvta.to.shared.u64 t, %1; cvt.u32.u64 %0, t; }" : "=r"(a) : "l"(p));
    return a;
}

__device__ __forceinline__ uint32_t pack_bf16(__nv_bfloat16 a, __nv_bfloat16 b) {
    return (uint32_t)__bfloat16_as_ushort(a) | ((uint32_t)__bfloat16_as_ushort(b) << 16);
}

__device__ __forceinline__ void split1(float v, __nv_bfloat16& h, __nv_bfloat16& l) {
    h = __float2bfloat16_rn(v);
    l = __float2bfloat16_rn(v - __bfloat162float(h));
}

#define MMA_BF16(C, A0, A1, A2, A3, B0, B1) \
    asm volatile( \
        "mma.sync.aligned.m16n8k16.row.col.f32.bf16.bf16.f32 " \
        "{%0,%1,%2,%3}, {%4,%5,%6,%7}, {%8,%9}, {%0,%1,%2,%3};" \
        : "+f"((C)[0]), "+f"((C)[1]), "+f"((C)[2]), "+f"((C)[3]) \
        : "r"(A0), "r"(A1), "r"(A2), "r"(A3), "r"(B0), "r"(B1))

__device__ __forceinline__ void ldsm4(uint32_t* r, uint32_t addr) {
    asm volatile("ldmatrix.sync.aligned.m8n8.x4.shared.b16 {%0,%1,%2,%3}, [%4];"
        : "=r"(r[0]), "=r"(r[1]), "=r"(r[2]), "=r"(r[3]) : "r"(addr));
}
__device__ __forceinline__ void ldsm4t(uint32_t* r, uint32_t addr) {
    asm volatile("ldmatrix.sync.aligned.m8n8.x4.trans.shared.b16 {%0,%1,%2,%3}, [%4];"
        : "=r"(r[0]), "=r"(r[1]), "=r"(r[2]), "=r"(r[3]) : "r"(addr));
}

// shared-memory pitch (bf16 elements): 72 -> 144B rows -> conflict-free LDSM
#define GP 72
#define PLANE (128 * GP * 2)          // 18432 bytes per 128-row plane
#define TOFF  (16 * GP * 2)           // byte offset of 16 rows = 2304

// ============================================================================
// fused fp32 -> bf16 hi/lo split over {x, z, wq, wk, wo}
// ============================================================================
#define NX ((size_t)MROWS * DD)       // 4194304
#define NW ((size_t)DD * DD)          // 1048576

__global__ __launch_bounds__(256) void cvt_split_all(
    const float* __restrict__ x, const float* __restrict__ z,
    const float* __restrict__ wq, const float* __restrict__ wk,
    const float* __restrict__ wo)
{
    const size_t i4 = ((size_t)blockIdx.x * 256 + threadIdx.x) * 4;
    const float* src;
    __nv_bfloat16 *hi, *lo;
    if (i4 < NX)               { src = x  + i4;                 hi = g_Xh + i4;                 lo = g_Xl + i4; }
    else if (i4 < 2 * NX)      { size_t j = i4 - NX;            src = z  + j; hi = g_Zh + j;    lo = g_Zl + j; }
    else if (i4 < 2 * NX + NW) { size_t j = i4 - 2 * NX;        src = wq + j; hi = g_Wqh + j;   lo = g_Wql + j; }
    else if (i4 < 2 * NX + 2 * NW) { size_t j = i4 - 2 * NX - NW; src = wk + j; hi = g_Wkh + j; lo = g_Wkl + j; }
    else                       { size_t j = i4 - 2 * NX - 2 * NW; src = wo + j; hi = g_Woh + j; lo = g_Wol + j; }

    const float4 v = *(const float4*)src;
    __nv_bfloat16 h0, h1, h2, h3, l0, l1, l2, l3;
    split1(v.x, h0, l0); split1(v.y, h1, l1);
    split1(v.z, h2, l2); split1(v.w, h3, l3);
    uint2 ph, pl;
    ph.x = pack_bf16(h0, h1); ph.y = pack_bf16(h2, h3);
    pl.x = pack_bf16(l0, l1); pl.y = pack_bf16(l2, l3);
    *(uint2*)hi = ph;
    *(uint2*)lo = pl;
}

// ============================================================================
// bf16x3 GEMM (ldmatrix frags, reg-pipelined loads): Y = A @ W^T + bias
// 512 thr / 16 warps, CTA 128x128, warp 32x32, K-chunk 64
// ============================================================================
#define GEMM_SMEM (4 * PLANE)         // 73728

template<bool OUTF32>
__global__ void __launch_bounds__(512, 1) gemm_pre(
    const __nv_bfloat16* __restrict__ Ah_g, const __nv_bfloat16* __restrict__ Al_g,
    const __nv_bfloat16* __restrict__ Wh_g, const __nv_bfloat16* __restrict__ Wl_g,
    const float* __restrict__ bias,
    float* __restrict__ Y,
    __nv_bfloat16* __restrict__ Yh, __nv_bfloat16* __restrict__ Yl,
    int K, int N)
{
    extern __shared__ char sm[];
    const uint32_t sb = smem_u32(sm);
    __nv_bfloat16* smAh = (__nv_bfloat16*)(sm);
    __nv_bfloat16* smAl = (__nv_bfloat16*)(sm + PLANE);
    __nv_bfloat16* smWh = (__nv_bfloat16*)(sm + 2 * PLANE);
    __nv_bfloat16* smWl = (__nv_bfloat16*)(sm + 3 * PLANE);

    const int tid = threadIdx.x;
    const int lane = tid & 31;
    const int wid = tid >> 5;
    const int wy = wid >> 2;
    const int wx = wid & 3;
    const int m0 = blockIdx.y * 128;
    const int n0 = blockIdx.x * 128;

    const int srow = tid >> 2;
    const int sk0 = (tid & 3) << 4;
    const __nv_bfloat16* pAh = Ah_g + (size_t)(m0 + srow) * K + sk0;
    const __nv_bfloat16* pAl = Al_g + (size_t)(m0 + srow) * K + sk0;
    const __nv_bfloat16* pWh = Wh_g + (size_t)(n0 + srow) * K + sk0;
    const __nv_bfloat16* pWl = Wl_g + (size_t)(n0 + srow) * K + sk0;
    const int sidx = srow * GP + sk0;

    const int lr = lane & 7;
    const int lm01 = (lane >> 3) & 1;
    const int lm23 = lane >> 4;
    const uint32_t aA = sb + (uint32_t)((((wy * 32 + lm01 * 8 + lr) * GP) + lm23 * 8) << 1);
    const uint32_t aW = sb + 2 * PLANE +
        (uint32_t)((((wx * 32 + lm23 * 8 + lr) * GP) + lm01 * 8) << 1);

    float acc[2][4][4];
#pragma unroll
    for (int t = 0; t < 2; t++)
#pragma unroll
        for (int u = 0; u < 4; u++)
#pragma unroll
            for (int i = 0; i < 4; i++) acc[t][u][i] = 0.f;

    const int r8 = lane >> 2;
    const int q2 = (lane & 3) << 1;
    const int nchunk = K >> 6;

    uint4 rg[8];
    auto loadregs = [&](int c) {
        const int kc = c << 6;
        rg[0] = *(const uint4*)(pAh + kc); rg[1] = *(const uint4*)(pAh + kc + 8);
        rg[2] = *(const uint4*)(pAl + kc); rg[3] = *(const uint4*)(pAl + kc + 8);
        rg[4] = *(const uint4*)(pWh + kc); rg[5] = *(const uint4*)(pWh + kc + 8);
        rg[6] = *(const uint4*)(pWl + kc); rg[7] = *(const uint4*)(pWl + kc + 8);
    };

    loadregs(0);
    for (int c = 0; c < nchunk; c++) {
        if (c > 0) __syncthreads();            // prev MMA done reading smem
        *(uint4*)(smAh + sidx)     = rg[0]; *(uint4*)(smAh + sidx + 8) = rg[1];
        *(uint4*)(smAl + sidx)     = rg[2]; *(uint4*)(smAl + sidx + 8) = rg[3];
        *(uint4*)(smWh + sidx)     = rg[4]; *(uint4*)(smWh + sidx + 8) = rg[5];
        *(uint4*)(smWl + sidx)     = rg[6]; *(uint4*)(smWl + sidx + 8) = rg[7];
        __syncthreads();
        if (c + 1 < nchunk) loadregs(c + 1);   // LDG in flight during MMAs

#pragma unroll
        for (int ks = 0; ks < 4; ks++) {
            const uint32_t kb = (uint32_t)ks << 5;
            uint32_t ahf[2][4], alf[2][4];
            ldsm4(ahf[0], aA + kb);
            ldsm4(ahf[1], aA + TOFF + kb);
            ldsm4(alf[0], aA + PLANE + kb);
            ldsm4(alf[1], aA + PLANE + TOFF + kb);
            uint32_t bhf[4][2], blf[4][2], tmp[4];
            ldsm4(tmp, aW + kb);
            bhf[0][0] = tmp[0]; bhf[0][1] = tmp[1]; bhf[1][0] = tmp[2]; bhf[1][1] = tmp[3];
            ldsm4(tmp, aW + TOFF + kb);
            bhf[2][0] = tmp[0]; bhf[2][1] = tmp[1]; bhf[3][0] = tmp[2]; bhf[3][1] = tmp[3];
            ldsm4(tmp, aW + PLANE + kb);
            blf[0][0] = tmp[0]; blf[0][1] = tmp[1]; blf[1][0] = tmp[2]; blf[1][1] = tmp[3];
            ldsm4(tmp, aW + PLANE + TOFF + kb);
            blf[2][0] = tmp[0]; blf[2][1] = tmp[1]; blf[3][0] = tmp[2]; blf[3][1] = tmp[3];
#pragma unroll
            for (int u = 0; u < 4; u++) {
#pragma unroll
                for (int t = 0; t < 2; t++) {
                    MMA_BF16(acc[t][u], ahf[t][0], ahf[t][1], ahf[t][2], ahf[t][3],
                             bhf[u][0], bhf[u][1]);
                    MMA_BF16(acc[t][u], ahf[t][0], ahf[t][1], ahf[t][2], ahf[t][3],
                             blf[u][0], blf[u][1]);
                    MMA_BF16(acc[t][u], alf[t][0], alf[t][1], alf[t][2], alf[t][3],
                             bhf[u][0], bhf[u][1]);
                }
            }
        }
    }

#pragma unroll
    for (int t = 0; t < 2; t++) {
        const int r0 = m0 + wy * 32 + t * 16 + r8;
#pragma unroll
        for (int u = 0; u < 4; u++) {
            const int col = n0 + wx * 32 + u * 8 + q2;
            const float b0 = bias[col], b1 = bias[col + 1];
            const float v00 = acc[t][u][0] + b0, v01 = acc[t][u][1] + b1;
            const float v10 = acc[t][u][2] + b0, v11 = acc[t][u][3] + b1;
            if (OUTF32) {
                *(float2*)(Y + (size_t)r0 * N + col) = make_float2(v00, v01);
                *(float2*)(Y + (size_t)(r0 + 8) * N + col) = make_float2(v10, v11);
            } else {
                __nv_bfloat16 h0, h1, l0, l1;
                split1(v00, h0, l0); split1(v01, h1, l1);
                *(uint32_t*)(Yh + (size_t)r0 * N + col) = pack_bf16(h0, h1);
                *(uint32_t*)(Yl + (size_t)r0 * N + col) = pack_bf16(l0, l1);
                split1(v10, h0, l0); split1(v11, h1, l1);
                *(uint32_t*)(Yh + (size_t)(r0 + 8) * N + col) = pack_bf16(h0, h1);
                *(uint32_t*)(Yl + (size_t)(r0 + 8) * N + col) = pack_bf16(l0, l1);
            }
        }
    }
}

// ============================================================================
// scores: S = (Q.K^T)*0.125, 128x128 causal tiles, ldmatrix fragments
// ============================================================================
#define SCORES_SMEM (4 * PLANE)       // 73728

__global__ void __launch_bounds__(512, 1) scores_mma(void)
{
    int idx = blockIdx.x;
    int qt = 0;
    while ((qt + 1) * (qt + 2) / 2 <= idx) qt++;
    const int kt = idx - qt * (qt + 1) / 2;
    const int bh = blockIdx.y;
    const int b = bh >> 4;
    const int h = bh & 15;
    const int q0 = qt << 7;
    const int k0g = kt << 7;

    extern __shared__ char sm[];
    const uint32_t sb = smem_u32(sm);
    __nv_bfloat16* Qh = (__nv_bfloat16*)(sm);
    __nv_bfloat16* Ql = (__nv_bfloat16*)(sm + PLANE);
    __nv_bfloat16* Kh = (__nv_bfloat16*)(sm + 2 * PLANE);
    __nv_bfloat16* Kl = (__nv_bfloat16*)(sm + 3 * PLANE);

    const int tid = threadIdx.x;
    const int lane = tid & 31;
    const int wid = tid >> 5;
    const int wy = wid >> 2;
    const int wx = wid & 3;

    {
        const int srow = tid >> 2;
        const int sk0 = (tid & 3) << 4;
        const size_t qoff = ((size_t)b * SS + q0 + srow) * DD + h * DK + sk0;
        const size_t koff = ((size_t)b * SS + k0g + srow) * DD + h * DK + sk0;
        const int sidx = srow * GP + sk0;
        *(uint4*)(Qh + sidx)     = *(const uint4*)(g_Qh + qoff);
        *(uint4*)(Qh + sidx + 8) = *(const uint4*)(g_Qh + qoff + 8);
        *(uint4*)(Ql + sidx)     = *(const uint4*)(g_Ql + qoff);
        *(uint4*)(Ql + sidx + 8) = *(const uint4*)(g_Ql + qoff + 8);
        *(uint4*)(Kh + sidx)     = *(const uint4*)(g_Kh + koff);
        *(uint4*)(Kh + sidx + 8) = *(const uint4*)(g_Kh + koff + 8);
        *(uint4*)(Kl + sidx)     = *(const uint4*)(g_Kl + koff);
        *(uint4*)(Kl + sidx + 8) = *(const uint4*)(g_Kl + koff + 8);
    }
    __syncthreads();

    const int lr = lane & 7;
    const int lm01 = (lane >> 3) & 1;
    const int lm23 = lane >> 4;
    const uint32_t aQ = sb + (uint32_t)((((wy * 32 + lm01 * 8 + lr) * GP) + lm23 * 8) << 1);
    const uint32_t aK = sb + 2 * PLANE +
        (uint32_t)((((wx * 32 + lm23 * 8 + lr) * GP) + lm01 * 8) << 1);

    float acc[2][4][4];
#pragma unroll
    for (int t = 0; t < 2; t++)
#pragma unroll
        for (int u = 0; u < 4; u++)
#pragma unroll
            for (int i = 0; i < 4; i++) acc[t][u][i] = 0.f;

    const int r8 = lane >> 2;
    const int q2 = (lane & 3) << 1;

#pragma unroll
    for (int ks = 0; ks < 4; ks++) {
        const uint32_t kb = (uint32_t)ks << 5;
        uint32_t ahf[2][4], alf[2][4];
        ldsm4(ahf[0], aQ + kb);
        ldsm4(ahf[1], aQ + TOFF + kb);
        ldsm4(alf[0], aQ + PLANE + kb);
        ldsm4(alf[1], aQ + PLANE + TOFF + kb);
        uint32_t bhf[4][2], blf[4][2], tmp[4];
        ldsm4(tmp, aK + kb);
        bhf[0][0] = tmp[0]; bhf[0][1] = tmp[1]; bhf[1][0] = tmp[2]; bhf[1][1] = tmp[3];
        ldsm4(tmp, aK + TOFF + kb);
        bhf[2][0] = tmp[0]; bhf[2][1] = tmp[1]; bhf[3][0] = tmp[2]; bhf[3][1] = tmp[3];
        ldsm4(tmp, aK + PLANE + kb);
        blf[0][0] = tmp[0]; blf[0][1] = tmp[1]; blf[1][0] = tmp[2]; blf[1][1] = tmp[3];
        ldsm4(tmp, aK + PLANE + TOFF + kb);
        blf[2][0] = tmp[0]; blf[2][1] = tmp[1]; blf[3][0] = tmp[2]; blf[3][1] = tmp[3];
#pragma unroll
        for (int u = 0; u < 4; u++) {
#pragma unroll
            for (int t = 0; t < 2; t++) {
                MMA_BF16(acc[t][u], ahf[t][0], ahf[t][1], ahf[t][2], ahf[t][3],
                         bhf[u][0], bhf[u][1]);
                MMA_BF16(acc[t][u], ahf[t][0], ahf[t][1], ahf[t][2], ahf[t][3],
                         blf[u][0], blf[u][1]);
                MMA_BF16(acc[t][u], alf[t][0], alf[t][1], alf[t][2], alf[t][3],
                         bhf[u][0], bhf[u][1]);
            }
        }
    }

    const float scale = 0.125f;
#pragma unroll
    for (int t = 0; t < 2; t++) {
        const int r0 = q0 + wy * 32 + t * 16 + r8;
#pragma unroll
        for (int u = 0; u < 4; u++) {
            const int col = k0g + wx * 32 + u * 8 + q2;
            float2 v0, v1;
            v0.x = acc[t][u][0] * scale; v0.y = acc[t][u][1] * scale;
            v1.x = acc[t][u][2] * scale; v1.y = acc[t][u][3] * scale;
            *(float2*)(g_S + ((size_t)bh * SS + r0) * SS + col) = v0;
            *(float2*)(g_S + ((size_t)bh * SS + r0 + 8) * SS + col) = v1;
        }
    }
}

// ============================================================================
// fused softmax + AW (packed 2-wide): one block per (b,q), loops over 16 heads
// ============================================================================
__global__ __launch_bounds__(512) void softmax_aw(float* __restrict__ AW)
{
    const int q = blockIdx.x & (SS - 1);
    const int b = blockIdx.x >> 11;
    const int len = q + 1;
    const int bound = ((q >> 7) + 1) << 7;

    __shared__ float buf[SS];
    __shared__ float awr[SS];
    __shared__ float red[16];
    __shared__ float s_bcast;

    const int tid = threadIdx.x;
    const int lane = tid & 31, warp = tid >> 5;
    const int tid2 = tid << 1;

    for (int k = tid2; k < bound; k += 1024) {
        awr[k] = 0.f; awr[k + 1] = 0.f;
    }
    __syncthreads();

    for (int h = 0; h < HH; h++) {
        const float* Srow = g_S + ((size_t)(b * HH + h) * SS + q) * SS;

        float m = -INFINITY;
        for (int k = tid2; k < len; k += 1024) {
            const float2 v = *(const float2*)(Srow + k);
            buf[k] = v.x;
            m = fmaxf(m, v.x);
            if (k + 1 < len) { buf[k + 1] = v.y; m = fmaxf(m, v.y); }
        }
#pragma unroll
        for (int o = 16; o; o >>= 1) m = fmaxf(m, __shfl_xor_sync(0xFFFFFFFFu, m, o));
        if (lane == 0) red[warp] = m;
        __syncthreads();
        if (tid == 0) {
            float t = red[0];
#pragma unroll
            for (int i = 1; i < 16; i++) t = fmaxf(t, red[i]);
            s_bcast = t;
        }
        __syncthreads();
        const float rowmax = s_bcast;
        __syncthreads();

        float s = 0.f;
        for (int k = tid2; k < len; k += 1024) {
            const float e0 = __expf(buf[k] - rowmax);
            buf[k] = e0; s += e0;
            if (k + 1 < len) {
                const float e1 = __expf(buf[k + 1] - rowmax);
                buf[k + 1] = e1; s += e1;
            }
        }
#pragma unroll
        for (int o = 16; o; o >>= 1) s += __shfl_xor_sync(0xFFFFFFFFu, s, o);
        if (lane == 0) red[warp] = s;
        __syncthreads();
        if (tid == 0) {
            float t = 0.f;
#pragma unroll
            for (int i = 0; i < 16; i++) t += red[i];
            s_bcast = t;
        }
        __syncthreads();
        const float inv = 1.0f / s_bcast;

        __nv_bfloat16* Ph = g_Ph + ((size_t)(b * HH + h) * SS + q) * SS;
        __nv_bfloat16* Pl = g_Pl + ((size_t)(b * HH + h) * SS + q) * SS;
        for (int k = tid2; k < bound; k += 1024) {
            const float v0 = (k < len) ? buf[k] * inv : 0.f;
            const float v1 = (k + 1 < len) ? buf[k + 1] * inv : 0.f;
            __nv_bfloat16 h0, h1, l0, l1;
            split1(v0, h0, l0); split1(v1, h1, l1);
            *(uint32_t*)(Ph + k) = pack_bf16(h0, h1);
            *(uint32_t*)(Pl + k) = pack_bf16(l0, l1);
            awr[k] += v0; awr[k + 1] += v1;
        }
        __syncthreads();
    }

    float* AWrow = AW + ((size_t)b * SS + q) * SS;
    for (int k = tid2; k < SS; k += 1024) {
        float2 o;
        o.x = (k < bound) ? awr[k] : 0.f;
        o.y = (k + 1 < bound) ? awr[k + 1] : 0.f;
        *(float2*)(AWrow + k) = o;
    }
}

// ============================================================================
// pv: C = P @ V (V = K planes), ldmatrix frags, reg-pipelined loads
// CTA: (qt128, bh), 512 thr, warp tile 16x32
// ============================================================================
#define VPLANE (64 * GP * 2)                  // 9216
#define PV_SMEM (2 * PLANE + 2 * VPLANE)      // 55296

__global__ void __launch_bounds__(512, 1) pv_mma(void)
{
    const int qt = blockIdx.x;
    const int bh = blockIdx.y;
    const int b = bh >> 4;
    const int h = bh & 15;
    const int q0 = qt << 7;

    extern __shared__ char sm[];
    const uint32_t sb = smem_u32(sm);
    __nv_bfloat16* Ph = (__nv_bfloat16*)(sm);
    __nv_bfloat16* Pl = (__nv_bfloat16*)(sm + PLANE);
    __nv_bfloat16* Vh = (__nv_bfloat16*)(sm + 2 * PLANE);
    __nv_bfloat16* Vl = (__nv_bfloat16*)(sm + 2 * PLANE + VPLANE);

    const int tid = threadIdx.x;
    const int lane = tid & 31;
    const int wid = tid >> 5;
    const int wy = wid >> 1;
    const int wx = wid & 1;

    const int lr = lane & 7;
    const int lm01 = (lane >> 3) & 1;
    const int lm23 = lane >> 4;
    const uint32_t aP = sb + (uint32_t)((((wy * 16 + lm01 * 8 + lr) * GP) + lm23 * 8) << 1);
    const uint32_t aV = sb + 2 * PLANE +
        (uint32_t)((((lm01 * 8 + lr) * GP) + wx * 32 + lm23 * 8) << 1);

    const int r8 = lane >> 2;
    const int q2 = (lane & 3) << 1;

    float acc[4][4];
#pragma unroll
    for (int u = 0; u < 4; u++)
#pragma unroll
        for (int i = 0; i < 4; i++) acc[u][i] = 0.f;

    const int prow_s = tid >> 2;
    const int pk0 = (tid & 3) << 4;
    const int krow = tid >> 3;
    const int vd0 = (tid & 7) << 3;

    const int nchunk = 2 * qt + 2;
    uint4 rp[4], rv[2];
    auto loadregs = [&](int kt) {
        const int kc = kt << 6;
        const size_t poff = ((size_t)bh * SS + q0 + prow_s) * SS + kc + pk0;
        rp[0] = *(const uint4*)(g_Ph + poff);
        rp[1] = *(const uint4*)(g_Ph + poff + 8);
        rp[2] = *(const uint4*)(g_Pl + poff);
        rp[3] = *(const uint4*)(g_Pl + poff + 8);
        const size_t voff = ((size_t)b * SS + kc + krow) * DD + h * DK + vd0;
        rv[0] = *(const uint4*)(g_Kh + voff);
        rv[1] = *(const uint4*)(g_Kl + voff);
    };

    loadregs(0);
    for (int kt = 0; kt < nchunk; kt++) {
        if (kt > 0) __syncthreads();
        {
            const int sidx = prow_s * GP + pk0;
            *(uint4*)(Ph + sidx)     = rp[0];
            *(uint4*)(Ph + sidx + 8) = rp[1];
            *(uint4*)(Pl + sidx)     = rp[2];
            *(uint4*)(Pl + sidx + 8) = rp[3];
            const int vidx = krow * GP + vd0;
            *(uint4*)(Vh + vidx) = rv[0];
            *(uint4*)(Vl + vidx) = rv[1];
        }
        __syncthreads();
        if (kt + 1 < nchunk) loadregs(kt + 1);

#pragma unroll
        for (int ks = 0; ks < 4; ks++) {
            const uint32_t kb = (uint32_t)ks << 5;
            const uint32_t vkb = (uint32_t)ks * TOFF;
            uint32_t ahf[4], alf[4];
            ldsm4(ahf, aP + kb);
            ldsm4(alf, aP + PLANE + kb);
            uint32_t bhf[4][2], blf[4][2], tmp[4];
            ldsm4t(tmp, aV + vkb);
            bhf[0][0] = tmp[0]; bhf[0][1] = tmp[1]; bhf[1][0] = tmp[2]; bhf[1][1] = tmp[3];
            ldsm4t(tmp, aV + vkb + 32);
            bhf[2][0] = tmp[0]; bhf[2][1] = tmp[1]; bhf[3][0] = tmp[2]; bhf[3][1] = tmp[3];
            ldsm4t(tmp, aV + VPLANE + vkb);
            blf[0][0] = tmp[0]; blf[0][1] = tmp[1]; blf[1][0] = tmp[2]; blf[1][1] = tmp[3];
            ldsm4t(tmp, aV + VPLANE + vkb + 32);
            blf[2][0] = tmp[0]; blf[2][1] = tmp[1]; blf[3][0] = tmp[2]; blf[3][1] = tmp[3];
#pragma unroll
            for (int u = 0; u < 4; u++) {
                MMA_BF16(acc[u], ahf[0], ahf[1], ahf[2], ahf[3], bhf[u][0], bhf[u][1]);
                MMA_BF16(acc[u], ahf[0], ahf[1], ahf[2], ahf[3], blf[u][0], blf[u][1]);
                MMA_BF16(acc[u], alf[0], alf[1], alf[2], alf[3], bhf[u][0], bhf[u][1]);
            }
        }
    }

    // epilogue -> C bf16 hi/lo planes
    const int r0 = q0 + wy * 16 + r8;
#pragma unroll
    for (int u = 0; u < 4; u++) {
        const int d = wx * 32 + u * 8 + q2;
        const size_t o0 = ((size_t)b * SS + r0) * DD + h * DK + d;
        const size_t o1 = ((size_t)b * SS + r0 + 8) * DD + h * DK + d;
        __nv_bfloat16 h0, h1, l0, l1;
        split1(acc[u][0], h0, l0); split1(acc[u][1], h1, l1);
        *(uint32_t*)(g_Ch + o0) = pack_bf16(h0, h1);
        *(uint32_t*)(g_Cl + o0) = pack_bf16(l0, l1);
        split1(acc[u][2], h0, l0); split1(acc[u][3], h1, l1);
        *(uint32_t*)(g_Ch + o1) = pack_bf16(h0, h1);
        *(uint32_t*)(g_Cl + o1) = pack_bf16(l0, l1);
    }
}

// ============================================================================
// launch
// ============================================================================
extern "C" void kernel_launch(void* const* d_in, const int* in_sizes, int n_in,
                              void* d_out, int out_size)
{
    const float* x    = (const float*)d_in[0];
    const float* z    = (const float*)d_in[1];
    // d_in[2] = mask (causal tril; handled analytically)
    const float* wq_w = (const float*)d_in[3];
    const float* wq_b = (const float*)d_in[4];
    const float* wk_w = (const float*)d_in[5];
    const float* wk_b = (const float*)d_in[6];
    // d_in[7], d_in[8] = wv (dead param in reference: v uses wk)
    const float* wo_w = (const float*)d_in[9];
    const float* wo_b = (const float*)d_in[10];

    float* out = (float*)d_out;                              // [B,S,D]
    float* AW  = out + (size_t)BB * SS * DD;                 // [B,S,S]

    __nv_bfloat16 *pXh, *pXl, *pZh, *pZl, *pQh, *pQl, *pKh, *pKl, *pCh, *pCl;
    __nv_bfloat16 *pWqh, *pWql, *pWkh, *pWkl, *pWoh, *pWol;
    cudaGetSymbolAddress((void**)&pXh, g_Xh); cudaGetSymbolAddress((void**)&pXl, g_Xl);
    cudaGetSymbolAddress((void**)&pZh, g_Zh); cudaGetSymbolAddress((void**)&pZl, g_Zl);
    cudaGetSymbolAddress((void**)&pQh, g_Qh); cudaGetSymbolAddress((void**)&pQl, g_Ql);
    cudaGetSymbolAddress((void**)&pKh, g_Kh); cudaGetSymbolAddress((void**)&pKl, g_Kl);
    cudaGetSymbolAddress((void**)&pCh, g_Ch); cudaGetSymbolAddress((void**)&pCl, g_Cl);
    cudaGetSymbolAddress((void**)&pWqh, g_Wqh); cudaGetSymbolAddress((void**)&pWql, g_Wql);
    cudaGetSymbolAddress((void**)&pWkh, g_Wkh); cudaGetSymbolAddress((void**)&pWkl, g_Wkl);
    cudaGetSymbolAddress((void**)&pWoh, g_Woh); cudaGetSymbolAddress((void**)&pWol, g_Wol);

    static int smem_set = 0;
    if (!smem_set) {
        cudaFuncSetAttribute(gemm_pre<true>,  cudaFuncAttributeMaxDynamicSharedMemorySize, GEMM_SMEM);
        cudaFuncSetAttribute(gemm_pre<false>, cudaFuncAttributeMaxDynamicSharedMemorySize, GEMM_SMEM);
        cudaFuncSetAttribute(scores_mma, cudaFuncAttributeMaxDynamicSharedMemorySize, SCORES_SMEM);
        cudaFuncSetAttribute(pv_mma, cudaFuncAttributeMaxDynamicSharedMemorySize, PV_SMEM);
        smem_set = 1;
    }

    // split inputs + weights (one fused launch; 11534336 elements / 4 / 256)
    cvt_split_all<<<11264, 256>>>(x, z, wq_w, wk_w, wo_w);

    const dim3 gProj(DD / 128, MROWS / 128);                 // (8,32)
    gemm_pre<false><<<gProj, 512, GEMM_SMEM>>>(pXh, pXl, pWqh, pWql, wq_b,
                                               nullptr, pQh, pQl, DD, DD);
    gemm_pre<false><<<gProj, 512, GEMM_SMEM>>>(pZh, pZl, pWkh, pWkl, wk_b,
                                               nullptr, pKh, pKl, DD, DD);

    scores_mma<<<dim3(136, BHT), 512, SCORES_SMEM>>>();

    softmax_aw<<<BB * SS, 512>>>(AW);

    pv_mma<<<dim3(16, BHT), 512, PV_SMEM>>>();

    gemm_pre<true><<<gProj, 512, GEMM_SMEM>>>(pCh, pCl, pWoh, pWol, wo_b,
                                              out, nullptr, nullptr, DD, DD);
}